// round 1
// baseline (speedup 1.0000x reference)
#include <cuda_runtime.h>

typedef unsigned long long u64;

// Fixed problem dims: B=8, N=256, NODE=128, EDGE=16, HID=256, MSG=128
#define MAXROWS 2048

// Scratch (device globals; no allocation allowed). Packed float pairs.
__device__ u64 g_A[MAXROWS * 128];   // A[row][h]  = h @ W1[:128]  + b1   (pairs over h)
__device__ u64 g_Bv[MAXROWS * 128];  // Bv[row][h] = h @ W1[128:256]      (pairs over h)

__device__ __forceinline__ u64 fma2(u64 a, u64 b, u64 c) {
    u64 d; asm("fma.rn.f32x2 %0,%1,%2,%3;" : "=l"(d) : "l"(a), "l"(b), "l"(c)); return d;
}
__device__ __forceinline__ u64 add2(u64 a, u64 b) {
    u64 d; asm("add.rn.f32x2 %0,%1,%2;" : "=l"(d) : "l"(a), "l"(b)); return d;
}
__device__ __forceinline__ u64 pack2(float x, float y) {
    u64 d; asm("mov.b64 %0,{%1,%2};" : "=l"(d) : "f"(x), "f"(y)); return d;
}
__device__ __forceinline__ float2 unpack2(u64 v) {
    float2 f; asm("mov.b64 {%0,%1},%2;" : "=f"(f.x), "=f"(f.y) : "l"(v)); return f;
}
__device__ __forceinline__ u64 dup2(float x) { return pack2(x, x); }

// ---------------------------------------------------------------------------
// Precompute A = h @ W1a + b1 and Bv = h @ W1b, one node-row per block.
// 256 threads: q = t&127 -> output h-pair (2q,2q+1); s = t>>7 -> k half.
// ---------------------------------------------------------------------------
__global__ __launch_bounds__(256) void precompute_kernel(
    const float* __restrict__ h, const float* __restrict__ W1,
    const float* __restrict__ b1)
{
    __shared__ __align__(16) u64 hd[128];
    __shared__ u64 bufA[128];
    __shared__ u64 bufB[128];

    const int r = blockIdx.x;
    const int t = threadIdx.x;
    if (t < 128) hd[t] = dup2(h[(size_t)r * 128 + t]);
    __syncthreads();

    const int q = t & 127, s = t >> 7;
    const u64* W1p = (const u64*)W1;   // W1 pairs: W1[k*256 + 2q] == W1p[k*128+q]
    u64 accA = 0ull, accB = 0ull;
    const int k0 = s * 64;
#pragma unroll 8
    for (int k = k0; k < k0 + 64; k++) {
        u64 hk = hd[k];
        accA = fma2(hk, W1p[(size_t)k * 128 + q], accA);
        accB = fma2(hk, W1p[(size_t)(k + 128) * 128 + q], accB);
    }
    if (s == 1) { bufA[q] = accA; bufB[q] = accB; }
    __syncthreads();
    if (s == 0) {
        accA = add2(accA, bufA[q]);
        accB = add2(accB, bufB[q]);
        accA = add2(accA, ((const u64*)b1)[q]);
        g_A[(size_t)r * 128 + q]  = accA;
        g_Bv[(size_t)r * 128 + q] = accB;
    }
}

// ---------------------------------------------------------------------------
// Main fused kernel: one (b,i) per block, 256 threads.
//   S[h]   = sum_{j active} adj * relu(A[i,h] + Bv[j,h] + e[i,j]@W1c + b1)
//   agg[m] = S @ W2 + deg*b2
//   uh     = relu([h_i|agg] @ U1 + c1);  out = uh @ U2 + c2
// ---------------------------------------------------------------------------
__global__ __launch_bounds__(256) void mpnn_main(
    const float* __restrict__ h, const float* __restrict__ adj,
    const float* __restrict__ ef, const float* __restrict__ W1,
    const float* __restrict__ W2, const float* __restrict__ b2,
    const float* __restrict__ U1, const float* __restrict__ c1,
    const float* __restrict__ U2, const float* __restrict__ c2,
    float* __restrict__ out)
{
    __shared__ __align__(16) u64 e2s[256 * 16];   // edge slice, values duplicated (32 KB)
    __shared__ int   jlist[256];
    __shared__ float cav[256];
    __shared__ u64   sp[128];
    __shared__ u64   S_dup[256];
    __shared__ u64   x_dup[256];
    __shared__ u64   uh_dup[256];
    __shared__ u64   buf[256];
    __shared__ int   s_cnt;
    __shared__ float s_deg;

    const int row  = blockIdx.x;        // b*256 + i
    const int b    = row >> 8;
    const int t    = threadIdx.x;
    const int p    = t & 127;           // h-pair index (h0 = 2p)
    const int half = t >> 7;            // j-interleave half

    if (t == 0) { s_cnt = 0; s_deg = 0.f; }
    __syncthreads();

    // --- load edge slice e[b,i,:,:] (256x16 f32), store duplicated pairs ---
    {
        const float4* e4 = (const float4*)(ef + (size_t)row * 256 * 16);
#pragma unroll
        for (int it = 0; it < 4; it++) {
            int i4 = t + it * 256;
            float4 v = e4[i4];
            ulonglong2* d = (ulonglong2*)(e2s + (size_t)i4 * 4);
            d[0] = make_ulonglong2(dup2(v.x), dup2(v.y));
            d[1] = make_ulonglong2(dup2(v.z), dup2(v.w));
        }
    }
    // --- adjacency row: compact active senders + degree ---
    {
        float av = adj[(size_t)row * 256 + t];
        if (av != 0.f) {
            int pos = atomicAdd(&s_cnt, 1);
            jlist[pos] = t;
            cav[pos] = av;
            atomicAdd(&s_deg, av);
        }
    }
    if (t < 128) x_dup[t] = dup2(h[(size_t)row * 128 + t]);
    __syncthreads();

    const int   m   = s_cnt;
    const float deg = s_deg;

    // W1c pairs for this thread's h-pair, loop invariant -> registers
    u64 w2r[16];
    const u64* W1p = (const u64*)W1;
#pragma unroll
    for (int k = 0; k < 16; k++) w2r[k] = W1p[(size_t)(256 + k) * 128 + p];

    const u64 a2   = g_A[(size_t)row * 128 + p];
    const u64* BvB = g_Bv + (size_t)(b << 8) * 128;

    float Sx = 0.f, Sy = 0.f;
    for (int idx = half; idx < m; idx += 2) {
        int   j  = jlist[idx];
        float av = cav[idx];
        u64 bv2  = BvB[(size_t)j * 128 + p];
        u64 acc0 = add2(a2, bv2);
        u64 acc1 = 0ull;
        const ulonglong2* ep = (const ulonglong2*)(e2s + (size_t)j * 16);
#pragma unroll
        for (int k8 = 0; k8 < 8; k8++) {
            ulonglong2 ev = ep[k8];
            acc0 = fma2(ev.x, w2r[2 * k8], acc0);
            acc1 = fma2(ev.y, w2r[2 * k8 + 1], acc1);
        }
        float2 tv = unpack2(add2(acc0, acc1));
        Sx = fmaf(av, fmaxf(tv.x, 0.f), Sx);
        Sy = fmaf(av, fmaxf(tv.y, 0.f), Sy);
    }
    if (half == 1) sp[p] = pack2(Sx, Sy);
    __syncthreads();
    if (half == 0) {
        float2 o = unpack2(sp[p]);
        Sx += o.x; Sy += o.y;
        S_dup[2 * p]     = dup2(Sx);
        S_dup[2 * p + 1] = dup2(Sy);
    }
    __syncthreads();

    // --- agg = S @ W2 + deg*b2 : q=t&63 -> m-pair, s4=t>>6 -> 4-way k split ---
    {
        const int q = t & 63, s4 = t >> 6;
        const u64* W2p = (const u64*)W2;   // W2[k*128 + 2q] == W2p[k*64+q]
        u64 acc = 0ull;
        const int h0 = s4 * 64;
#pragma unroll 8
        for (int k = h0; k < h0 + 64; k++)
            acc = fma2(S_dup[k], W2p[(size_t)k * 64 + q], acc);
        buf[t] = acc;
    }
    __syncthreads();
    if (t < 64) {
        u64 tot = add2(add2(buf[t], buf[t + 64]), add2(buf[t + 128], buf[t + 192]));
        tot = fma2(dup2(deg), ((const u64*)b2)[t], tot);
        float2 v = unpack2(tot);
        x_dup[128 + 2 * t]     = dup2(v.x);
        x_dup[128 + 2 * t + 1] = dup2(v.y);
    }
    __syncthreads();

    // --- u_hidden = relu(x @ U1 + c1) : q=t&127 -> hh-pair, s2=t>>7 -> k half ---
    {
        const int q = t & 127, s2 = t >> 7;
        const u64* U1p = (const u64*)U1;   // U1[k*256 + 2q] == U1p[k*128+q]
        u64 acc = 0ull;
        const int k0 = s2 * 128;
#pragma unroll 8
        for (int k = k0; k < k0 + 128; k++)
            acc = fma2(x_dup[k], U1p[(size_t)k * 128 + q], acc);
        if (s2 == 1) buf[q] = acc;
        __syncthreads();
        if (s2 == 0) {
            acc = add2(acc, buf[q]);
            acc = add2(acc, ((const u64*)c1)[q]);
            float2 v = unpack2(acc);
            uh_dup[2 * q]     = dup2(fmaxf(v.x, 0.f));
            uh_dup[2 * q + 1] = dup2(fmaxf(v.y, 0.f));
        }
    }
    __syncthreads();

    // --- out = uh @ U2 + c2 : q=t&63 -> d-pair, 4-way k split ---
    {
        const int q = t & 63, s4 = t >> 6;
        const u64* U2p = (const u64*)U2;   // U2[k*128 + 2q] == U2p[k*64+q]
        u64 acc = 0ull;
        const int k0 = s4 * 64;
#pragma unroll 8
        for (int k = k0; k < k0 + 64; k++)
            acc = fma2(uh_dup[k], U2p[(size_t)k * 64 + q], acc);
        buf[t] = acc;
    }
    __syncthreads();
    if (t < 64) {
        u64 tot = add2(add2(buf[t], buf[t + 64]), add2(buf[t + 128], buf[t + 192]));
        tot = add2(tot, ((const u64*)c2)[t]);
        ((u64*)out)[(size_t)row * 64 + t] = tot;
    }
}

extern "C" void kernel_launch(void* const* d_in, const int* in_sizes, int n_in,
                              void* d_out, int out_size)
{
    const float* h   = (const float*)d_in[0];
    const float* adj = (const float*)d_in[1];
    const float* ef  = (const float*)d_in[2];
    const float* W1  = (const float*)d_in[3];
    const float* b1  = (const float*)d_in[4];
    const float* W2  = (const float*)d_in[5];
    const float* b2  = (const float*)d_in[6];
    const float* U1  = (const float*)d_in[7];
    const float* c1  = (const float*)d_in[8];
    const float* U2  = (const float*)d_in[9];
    const float* c2  = (const float*)d_in[10];

    const int rows = in_sizes[0] / 128;   // B*N = 2048

    precompute_kernel<<<rows, 256>>>(h, W1, b1);
    mpnn_main<<<rows, 256>>>(h, adj, ef, W1, W2, b2, U1, c1, U2, c2, (float*)d_out);
}

// round 2
// speedup vs baseline: 1.4071x; 1.4071x over previous
#include <cuda_runtime.h>

typedef unsigned long long u64;

// Fixed problem dims: B=8, N=256, NODE=128, EDGE=16, HID=256, MSG=128
#define MAXROWS 2048

// Scratch (device globals). Packed float pairs.
__device__ u64 g_A[MAXROWS * 128];   // A[row][h]  = h @ W1[:128] + b1   (pairs over h)
__device__ u64 g_Bv[MAXROWS * 128];  // Bv[row][h] = h @ W1[128:256]     (pairs over h)

__device__ __forceinline__ u64 fma2(u64 a, u64 b, u64 c) {
    u64 d; asm("fma.rn.f32x2 %0,%1,%2,%3;" : "=l"(d) : "l"(a), "l"(b), "l"(c)); return d;
}
__device__ __forceinline__ u64 add2(u64 a, u64 b) {
    u64 d; asm("add.rn.f32x2 %0,%1,%2;" : "=l"(d) : "l"(a), "l"(b)); return d;
}
__device__ __forceinline__ u64 pack2(float x, float y) {
    u64 d; asm("mov.b64 %0,{%1,%2};" : "=l"(d) : "f"(x), "f"(y)); return d;
}
__device__ __forceinline__ float2 unpack2(u64 v) {
    float2 f; asm("mov.b64 {%0,%1},%2;" : "=f"(f.x), "=f"(f.y) : "l"(v)); return f;
}
__device__ __forceinline__ u64 dup2(float x) { return pack2(x, x); }

// ---------------------------------------------------------------------------
// Precompute A = h @ W1a + b1 and Bv = h @ W1b, one node-row per block.
// ---------------------------------------------------------------------------
__global__ __launch_bounds__(256) void precompute_kernel(
    const float* __restrict__ h, const float* __restrict__ W1,
    const float* __restrict__ b1)
{
    __shared__ __align__(16) u64 hd[128];
    __shared__ u64 bufA[128];
    __shared__ u64 bufB[128];

    const int r = blockIdx.x;
    const int t = threadIdx.x;
    if (t < 128) hd[t] = dup2(h[(size_t)r * 128 + t]);
    __syncthreads();

    const int q = t & 127, s = t >> 7;
    const u64* W1p = (const u64*)W1;   // W1 pairs: W1[k*256 + 2q] == W1p[k*128+q]
    u64 accA = 0ull, accB = 0ull;
    const int k0 = s * 64;
#pragma unroll 8
    for (int k = k0; k < k0 + 64; k++) {
        u64 hk = hd[k];
        accA = fma2(hk, W1p[(size_t)k * 128 + q], accA);
        accB = fma2(hk, W1p[(size_t)(k + 128) * 128 + q], accB);
    }
    if (s == 1) { bufA[q] = accA; bufB[q] = accB; }
    __syncthreads();
    if (s == 0) {
        accA = add2(accA, bufA[q]);
        accB = add2(accB, bufB[q]);
        accA = add2(accA, ((const u64*)b1)[q]);
        g_A[(size_t)r * 128 + q]  = accA;
        g_Bv[(size_t)r * 128 + q] = accB;
    }
}

// ---------------------------------------------------------------------------
// Main fused kernel: one (b,i) per block, 256 threads.
// Inner GEMM register-tiled 4j x 2h per thread-step, W1c dup'd in registers,
// edge slice compacted + transposed in smem (plain f32).
// ---------------------------------------------------------------------------
__global__ __launch_bounds__(256, 2) void mpnn_main(
    const float* __restrict__ h, const float* __restrict__ adj,
    const float* __restrict__ ef, const float* __restrict__ W1,
    const float* __restrict__ W2, const float* __restrict__ b2,
    const float* __restrict__ U1, const float* __restrict__ c1,
    const float* __restrict__ U2, const float* __restrict__ c2,
    float* __restrict__ out)
{
    __shared__ __align__(16) float eT[16][256];   // transposed compacted edges (16 KB)
    __shared__ __align__(16) int   jlist[256];
    __shared__ __align__(16) float cav[256];
    __shared__ __align__(16) u64   sp[128];
    __shared__ __align__(16) u64   S_dup[256];
    __shared__ __align__(16) u64   x_dup[256];
    __shared__ __align__(16) u64   uh_dup[256];
    __shared__ __align__(16) u64   buf[256];
    __shared__ int   wcnt[8];
    __shared__ float wsum[8];
    __shared__ int   s_m;
    __shared__ float s_deg;

    const int row  = blockIdx.x;        // b*256 + i
    const int b    = row >> 8;
    const int t    = threadIdx.x;
    const int p    = t & 127;           // h-pair index (h0 = 2p, h1 = 2p+1)
    const int half = t >> 7;            // j-interleave half
    const int w    = t >> 5;
    const int l    = t & 31;

    // --- deterministic adjacency compaction ---
    const float av = adj[(size_t)row * 256 + t];
    const unsigned mask = __ballot_sync(0xffffffffu, av != 0.f);
    float ds = av;
#pragma unroll
    for (int off = 16; off; off >>= 1) ds += __shfl_xor_sync(0xffffffffu, ds, off);
    if (l == 0) { wcnt[w] = __popc(mask); wsum[w] = ds; }
    if (t < 128) x_dup[t] = dup2(h[(size_t)row * 128 + t]);
    __syncthreads();
    if (t == 0) {
        int acc = 0; float d = 0.f;
#pragma unroll
        for (int i = 0; i < 8; i++) { int c = wcnt[i]; wcnt[i] = acc; acc += c; d += wsum[i]; }
        s_m = acc; s_deg = d;
    }
    __syncthreads();
    const int   m   = s_m;
    const float deg = s_deg;
    const int   mp  = (m + 7) & ~7;

    if (av != 0.f) {
        int pos = wcnt[w] + __popc(mask & ((1u << l) - 1u));
        jlist[pos] = t;
        cav[pos]   = av;
    }
    if (t >= m && t < mp) { jlist[t] = 0; cav[t] = 0.f; }
    __syncthreads();

    // --- stage compacted, transposed edge slice into eT ---
    if (t < mp) {
        if (t < m) {
            const int j = jlist[t];
            const float4* e4 = (const float4*)(ef + ((size_t)row * 256 + j) * 16);
            float4 v0 = e4[0], v1 = e4[1], v2 = e4[2], v3 = e4[3];
            eT[0][t]  = v0.x; eT[1][t]  = v0.y; eT[2][t]  = v0.z; eT[3][t]  = v0.w;
            eT[4][t]  = v1.x; eT[5][t]  = v1.y; eT[6][t]  = v1.z; eT[7][t]  = v1.w;
            eT[8][t]  = v2.x; eT[9][t]  = v2.y; eT[10][t] = v2.z; eT[11][t] = v2.w;
            eT[12][t] = v3.x; eT[13][t] = v3.y; eT[14][t] = v3.z; eT[15][t] = v3.w;
        } else {
#pragma unroll
            for (int k = 0; k < 16; k++) eT[k][t] = 0.f;
        }
    }
    __syncthreads();

    // --- W1c weights for this thread's 2 h-outputs, duplicated in registers ---
    u64 wd0[16], wd1[16];
    {
        const u64* W1p = (const u64*)W1;
#pragma unroll
        for (int k = 0; k < 16; k++) {
            float2 wp = unpack2(W1p[(size_t)(256 + k) * 128 + p]);
            wd0[k] = dup2(wp.x);
            wd1[k] = dup2(wp.y);
        }
    }
    const float2 a   = unpack2(g_A[(size_t)row * 128 + p]);
    const u64*   BvB = g_Bv + (size_t)(b << 8) * 128;

    float S0 = 0.f, S1 = 0.f;
    for (int jj = half * 4; jj < mp; jj += 8) {
        const int4   jl  = *(const int4*)&jlist[jj];
        const float4 avv = *(const float4*)&cav[jj];
        const u64 q0 = BvB[(size_t)jl.x * 128 + p];
        const u64 q1 = BvB[(size_t)jl.y * 128 + p];
        const u64 q2 = BvB[(size_t)jl.z * 128 + p];
        const u64 q3 = BvB[(size_t)jl.w * 128 + p];

        u64 acc00 = 0ull, acc01 = 0ull, acc10 = 0ull, acc11 = 0ull;
        const char* ecol = (const char*)&eT[0][jj];
#pragma unroll
        for (int k = 0; k < 16; k++) {
            ulonglong2 ev = *(const ulonglong2*)(ecol + k * 1024);
            acc00 = fma2(ev.x, wd0[k], acc00);
            acc01 = fma2(ev.y, wd0[k], acc01);
            acc10 = fma2(ev.x, wd1[k], acc10);
            acc11 = fma2(ev.y, wd1[k], acc11);
        }
        const float2 d00 = unpack2(acc00), d01 = unpack2(acc01);
        const float2 d10 = unpack2(acc10), d11 = unpack2(acc11);
        const float2 b0 = unpack2(q0), b1v = unpack2(q1);
        const float2 b2v = unpack2(q2), b3v = unpack2(q3);

        S0 = fmaf(avv.x, fmaxf(a.x + b0.x  + d00.x, 0.f), S0);
        S0 = fmaf(avv.y, fmaxf(a.x + b1v.x + d00.y, 0.f), S0);
        S0 = fmaf(avv.z, fmaxf(a.x + b2v.x + d01.x, 0.f), S0);
        S0 = fmaf(avv.w, fmaxf(a.x + b3v.x + d01.y, 0.f), S0);
        S1 = fmaf(avv.x, fmaxf(a.y + b0.y  + d10.x, 0.f), S1);
        S1 = fmaf(avv.y, fmaxf(a.y + b1v.y + d10.y, 0.f), S1);
        S1 = fmaf(avv.z, fmaxf(a.y + b2v.y + d11.x, 0.f), S1);
        S1 = fmaf(avv.w, fmaxf(a.y + b3v.y + d11.y, 0.f), S1);
    }

    if (half == 1) sp[p] = pack2(S0, S1);
    __syncthreads();
    if (half == 0) {
        float2 o = unpack2(sp[p]);
        S_dup[2 * p]     = dup2(S0 + o.x);
        S_dup[2 * p + 1] = dup2(S1 + o.y);
    }
    __syncthreads();

    // --- agg = S @ W2 + deg*b2 : q=t&63 -> m-pair, 4-way k split ---
    {
        const int q = t & 63, s4 = t >> 6;
        const u64* W2p = (const u64*)W2;   // W2[k*128 + 2q] == W2p[k*64+q]
        u64 acc = 0ull;
        const int h0 = s4 * 64;
#pragma unroll 8
        for (int k = h0; k < h0 + 64; k += 2) {
            ulonglong2 sv = *(const ulonglong2*)&S_dup[k];
            acc = fma2(sv.x, W2p[(size_t)k * 64 + q], acc);
            acc = fma2(sv.y, W2p[(size_t)(k + 1) * 64 + q], acc);
        }
        buf[t] = acc;
    }
    __syncthreads();
    if (t < 64) {
        u64 tot = add2(add2(buf[t], buf[t + 64]), add2(buf[t + 128], buf[t + 192]));
        tot = fma2(dup2(deg), ((const u64*)b2)[t], tot);
        float2 v = unpack2(tot);
        x_dup[128 + 2 * t]     = dup2(v.x);
        x_dup[128 + 2 * t + 1] = dup2(v.y);
    }
    __syncthreads();

    // --- u_hidden = relu(x @ U1 + c1) : q=t&127 -> hh-pair, 2-way k split ---
    {
        const int q = t & 127, s2 = t >> 7;
        const u64* U1p = (const u64*)U1;   // U1[k*256 + 2q] == U1p[k*128+q]
        u64 acc = 0ull;
        const int k0 = s2 * 128;
#pragma unroll 8
        for (int k = k0; k < k0 + 128; k += 2) {
            ulonglong2 xv = *(const ulonglong2*)&x_dup[k];
            acc = fma2(xv.x, U1p[(size_t)k * 128 + q], acc);
            acc = fma2(xv.y, U1p[(size_t)(k + 1) * 128 + q], acc);
        }
        if (s2 == 1) buf[q] = acc;
        __syncthreads();
        if (s2 == 0) {
            acc = add2(acc, buf[q]);
            acc = add2(acc, ((const u64*)c1)[q]);
            float2 v = unpack2(acc);
            uh_dup[2 * q]     = dup2(fmaxf(v.x, 0.f));
            uh_dup[2 * q + 1] = dup2(fmaxf(v.y, 0.f));
        }
    }
    __syncthreads();

    // --- out = uh @ U2 + c2 : q=t&63 -> d-pair, 4-way k split ---
    {
        const int q = t & 63, s4 = t >> 6;
        const u64* U2p = (const u64*)U2;   // U2[k*128 + 2q] == U2p[k*64+q]
        u64 acc = 0ull;
        const int k0 = s4 * 64;
#pragma unroll 8
        for (int k = k0; k < k0 + 64; k += 2) {
            ulonglong2 uv = *(const ulonglong2*)&uh_dup[k];
            acc = fma2(uv.x, U2p[(size_t)k * 64 + q], acc);
            acc = fma2(uv.y, U2p[(size_t)(k + 1) * 64 + q], acc);
        }
        buf[t] = acc;
    }
    __syncthreads();
    if (t < 64) {
        u64 tot = add2(add2(buf[t], buf[t + 64]), add2(buf[t + 128], buf[t + 192]));
        tot = add2(tot, ((const u64*)c2)[t]);
        ((u64*)out)[(size_t)row * 64 + t] = tot;
    }
}

extern "C" void kernel_launch(void* const* d_in, const int* in_sizes, int n_in,
                              void* d_out, int out_size)
{
    const float* h   = (const float*)d_in[0];
    const float* adj = (const float*)d_in[1];
    const float* ef  = (const float*)d_in[2];
    const float* W1  = (const float*)d_in[3];
    const float* b1  = (const float*)d_in[4];
    const float* W2  = (const float*)d_in[5];
    const float* b2  = (const float*)d_in[6];
    const float* U1  = (const float*)d_in[7];
    const float* c1  = (const float*)d_in[8];
    const float* U2  = (const float*)d_in[9];
    const float* c2  = (const float*)d_in[10];

    const int rows = in_sizes[0] / 128;   // B*N = 2048

    precompute_kernel<<<rows, 256>>>(h, W1, b1);
    mpnn_main<<<rows, 256>>>(h, adj, ef, W1, W2, b2, U1, c1, U2, c2, (float*)d_out);
}